// round 4
// baseline (speedup 1.0000x reference)
#include <cuda_runtime.h>
#include <cuda_fp16.h>
#include <math.h>

#define LL   1024
#define NN   16384
#define DD   512
#define RR   128
#define PEN  (-10000.0f)
#define STEPS 1023   // L-1 transitions

// ---------------- scratch (static __device__: no runtime allocation) ----------
__device__ float   d_HW[(size_t)NN * DD];            // 32 MB : H @ W
__device__ __half  d_E[(size_t)STEPS * RR * RR];     // 32 MB : exp(pair - colmax), layout [s][j][i]
__device__ float   d_M[STEPS * RR];                  // column max per (s, j)
__device__ int     d_cand[LL * RR];                  // top-128 indices per row (unsorted set)
__device__ float   d_lsm[LL * RR];                   // log_softmax(u[cand]) per row/slot
__device__ double  d_acc[2];                         // [0]=unary score, [1]=pair score
__device__ int     d_atype;                          // allowed dtype: 0=u8 1=i32 2=f32

// ---------------- helpers ------------------------------------------------------
__device__ __forceinline__ unsigned fkey(float f) {  // monotonic float->uint
    unsigned u = __float_as_uint(f);
    return (u & 0x80000000u) ? ~u : (u | 0x80000000u);
}
__device__ __forceinline__ bool mask_at(const void* aw, size_t idx, int t) {
    if (t == 0) return ((const unsigned char*)aw)[idx] != 0;
    if (t == 1) return ((const int*)aw)[idx] != 0;
    return ((const float*)aw)[idx] != 0.0f;
}

// ---------------- K0: init + allowed-dtype detection ---------------------------
__global__ void k_init(const unsigned* __restrict__ aw) {
    __shared__ int isF, isB;
    if (threadIdx.x == 0) { isF = 0; isB = 0; d_acc[0] = 0.0; d_acc[1] = 0.0; }
    __syncthreads();
    for (int i = threadIdx.x; i < 4096; i += blockDim.x) {
        unsigned w = aw[i];
        if (w == 0x3F800000u) isF = 1;                 // float 1.0 pattern
        else if (w != 0u && w != 1u) isB = 1;          // packed-byte pattern
    }
    __syncthreads();
    if (threadIdx.x == 0) d_atype = isF ? 2 : (isB ? 0 : 1);
}

// ---------------- K1: exact top-128 per row (radix select) + log_softmax -------
__global__ void k_topk(const float* __restrict__ U) {
    const int tid = threadIdx.x;
    const int row = blockIdx.x;
    const float* x = U + (size_t)row * NN;

    __shared__ unsigned bins[256];
    __shared__ unsigned s_prefix;
    __shared__ int s_rem, cntA, cntE;
    __shared__ int   cand_sh[RR];
    __shared__ float val_sh[RR];
    __shared__ int   eq_idx[64];
    __shared__ float red[16];

    if (tid == 0) { s_prefix = 0u; s_rem = RR; }
    if (tid < RR) { cand_sh[tid] = 0; val_sh[tid] = -INFINITY; }  // hedge

    for (int pass = 0; pass < 4; ++pass) {
        int shift = 24 - 8 * pass;
        bins[tid] = 0;
        __syncthreads();
        unsigned pmask = pass ? (0xFFFFFFFFu << (shift + 8)) : 0u;
        unsigned pref  = s_prefix;
        for (int i = tid; i < NN; i += 256) {
            unsigned k = fkey(x[i]);
            if ((k & pmask) == pref) atomicAdd(&bins[(k >> shift) & 0xFFu], 1u);
        }
        __syncthreads();
        if (tid == 0) {
            int r = s_rem;
            int b = 255;
            for (;;) {
                int c = (int)bins[b];
                if (c >= r) break;
                r -= c; --b;
            }
            s_prefix = pref | ((unsigned)b << shift);
            s_rem = r;
        }
        __syncthreads();
    }
    unsigned thresh = s_prefix;
    int remF = s_rem;                       // # threshold-valued elems to include
    if (tid == 0) { cntA = 0; cntE = 0; }
    __syncthreads();

    for (int i = tid; i < NN; i += 256) {
        float v = x[i];
        unsigned k = fkey(v);
        if (k > thresh) {
            int p = atomicAdd(&cntA, 1);
            cand_sh[p] = i; val_sh[p] = v;
        } else if (k == thresh) {
            int p = atomicAdd(&cntE, 1);
            if (p < 64) eq_idx[p] = i;
        }
    }
    __syncthreads();
    int nA = cntA;
    int nE = min(cntE, 64);
    if (tid < nE) {                          // first-index tie-break (jax top_k)
        int my = eq_idx[tid], rank = 0;
        for (int q = 0; q < nE; q++) rank += (eq_idx[q] < my);
        if (rank < remF) { cand_sh[nA + rank] = my; val_sh[nA + rank] = x[my]; }
    }
    __syncthreads();

    // log_softmax over the 128 selected values
    float v = (tid < RR) ? val_sh[tid] : -INFINITY;
    for (int o = 16; o > 0; o >>= 1) v = fmaxf(v, __shfl_xor_sync(~0u, v, o));
    if ((tid & 31) == 0) red[tid >> 5] = v;
    __syncthreads();
    if (tid == 0) {
        float m = red[0];
        for (int q = 1; q < 8; q++) m = fmaxf(m, red[q]);
        if (m == -INFINITY) m = 0.f;         // hedge
        red[0] = m;
    }
    __syncthreads();
    float mx = red[0];
    float e = (tid < RR) ? __expf(val_sh[tid] - mx) : 0.f;
    for (int o = 16; o > 0; o >>= 1) e += __shfl_xor_sync(~0u, e, o);
    if ((tid & 31) == 0) red[8 + (tid >> 5)] = e;
    __syncthreads();
    if (tid == 0) {
        float s = 0.f;
        for (int q = 0; q < 8; q++) s += red[8 + q];
        red[1] = mx + logf(fmaxf(s, 1e-30f));
    }
    __syncthreads();
    float lse = red[1];
    if (tid < RR) {
        d_cand[row * RR + tid] = cand_sh[tid];
        d_lsm[row * RR + tid]  = val_sh[tid] - lse;
    }
}

// ---------------- K2: HW = H @ W (fp32 tiled GEMM, 128x128x16 tiles) -----------
__global__ __launch_bounds__(256, 2)
void k_gemm_hw(const float* __restrict__ Hm, const float* __restrict__ W) {
    __shared__ float As[16][132];
    __shared__ float Bs[16][132];
    int tid = threadIdx.x;
    int nt = blockIdx.x, mt = blockIdx.y;
    int tx = tid & 15, ty = tid >> 4;

    float acc[8][8];
#pragma unroll
    for (int i = 0; i < 8; i++)
#pragma unroll
        for (int jj = 0; jj < 8; jj++) acc[i][jj] = 0.f;

    int r8 = tid >> 2;             // 0..63
    int k4 = (tid & 3) * 4;        // 0,4,8,12
    int bk  = tid >> 5;            // 0..7
    int bn4 = (tid & 31) * 4;      // 0..124

    for (int k0 = 0; k0 < DD; k0 += 16) {
#pragma unroll
        for (int e = 0; e < 2; e++) {
            int m = r8 + 64 * e;
            float4 a = *(const float4*)(Hm + (size_t)(mt * 128 + m) * DD + k0 + k4);
            As[k4 + 0][m] = a.x; As[k4 + 1][m] = a.y;
            As[k4 + 2][m] = a.z; As[k4 + 3][m] = a.w;
            int k = bk + 8 * e;
            float4 b = *(const float4*)(W + (size_t)(k0 + k) * DD + nt * 128 + bn4);
            *(float4*)&Bs[k][bn4] = b;
        }
        __syncthreads();
#pragma unroll
        for (int kk = 0; kk < 16; kk++) {
            float a[8], b[8];
            *(float4*)(a)     = *(float4*)&As[kk][ty * 8];
            *(float4*)(a + 4) = *(float4*)&As[kk][ty * 8 + 4];
            *(float4*)(b)     = *(float4*)&Bs[kk][tx * 8];
            *(float4*)(b + 4) = *(float4*)&Bs[kk][tx * 8 + 4];
#pragma unroll
            for (int i = 0; i < 8; i++)
#pragma unroll
                for (int jj = 0; jj < 8; jj++) acc[i][jj] += a[i] * b[jj];
        }
        __syncthreads();
    }
#pragma unroll
    for (int i = 0; i < 8; i++) {
        float4* dst = (float4*)(d_HW + (size_t)(mt * 128 + ty * 8 + i) * DD + nt * 128 + tx * 8);
        dst[0] = make_float4(acc[i][0], acc[i][1], acc[i][2], acc[i][3]);
        dst[1] = make_float4(acc[i][4], acc[i][5], acc[i][6], acc[i][7]);
    }
}

// ---------------- K3: pair = HW[prev] @ H[cur]^T, mask, colmax, exp -> fp16 ----
__global__ __launch_bounds__(256, 2)
void k_pair(const float* __restrict__ Hm, const void* __restrict__ aw) {
    int s = blockIdx.x;
    __shared__ float As[16][132];
    __shared__ float Bs[16][132];
    __shared__ int   prevs[RR], curs[RR];
    __shared__ float colred[16][128];
    __shared__ float Mj[128];

    int tid = threadIdx.x;
    if (tid < RR) {
        prevs[tid] = d_cand[s * RR + tid];
        curs[tid]  = d_cand[(s + 1) * RR + tid];
    }
    __syncthreads();

    int tx = tid & 15, ty = tid >> 4;
    float acc[8][8];
#pragma unroll
    for (int i = 0; i < 8; i++)
#pragma unroll
        for (int jj = 0; jj < 8; jj++) acc[i][jj] = 0.f;

    int r8 = tid >> 2;
    int k4 = (tid & 3) * 4;

    for (int k0 = 0; k0 < DD; k0 += 16) {
#pragma unroll
        for (int e = 0; e < 2; e++) {
            int m = r8 + 64 * e;
            int arow = prevs[m];
            float4 a = *(const float4*)(d_HW + (size_t)arow * DD + k0 + k4);
            As[k4 + 0][m] = a.x; As[k4 + 1][m] = a.y;
            As[k4 + 2][m] = a.z; As[k4 + 3][m] = a.w;
            int brow = curs[m];
            float4 b = *(const float4*)(Hm + (size_t)brow * DD + k0 + k4);
            Bs[k4 + 0][m] = b.x; Bs[k4 + 1][m] = b.y;
            Bs[k4 + 2][m] = b.z; Bs[k4 + 3][m] = b.w;
        }
        __syncthreads();
#pragma unroll
        for (int kk = 0; kk < 16; kk++) {
            float a[8], b[8];
            *(float4*)(a)     = *(float4*)&As[kk][ty * 8];
            *(float4*)(a + 4) = *(float4*)&As[kk][ty * 8 + 4];
            *(float4*)(b)     = *(float4*)&Bs[kk][tx * 8];
            *(float4*)(b + 4) = *(float4*)&Bs[kk][tx * 8 + 4];
#pragma unroll
            for (int i = 0; i < 8; i++)
#pragma unroll
                for (int jj = 0; jj < 8; jj++) acc[i][jj] += a[i] * b[jj];
        }
        __syncthreads();
    }

    // mask + penalty + per-thread column max
    int atype = d_atype;
    float cm[8];
#pragma unroll
    for (int dj = 0; dj < 8; dj++) cm[dj] = -INFINITY;
#pragma unroll
    for (int dj = 0; dj < 8; dj++) {
        int j = tx * 8 + dj;
        size_t base = (size_t)curs[j] * NN;
#pragma unroll
        for (int di = 0; di < 8; di++) {
            int pi = prevs[ty * 8 + di];
            if (!mask_at(aw, base + pi, atype)) acc[di][dj] += PEN;
            cm[dj] = fmaxf(cm[dj], acc[di][dj]);
        }
    }
#pragma unroll
    for (int dj = 0; dj < 8; dj++) colred[ty][tx * 8 + dj] = cm[dj];
    __syncthreads();
    if (tid < 128) {
        float m = colred[0][tid];
#pragma unroll
        for (int t = 1; t < 16; t++) m = fmaxf(m, colred[t][tid]);
        Mj[tid] = m;
        d_M[s * 128 + tid] = m;
    }
    __syncthreads();

    // E[s][j][i] = exp(pair - M_j), fp16, transposed layout for the scan
#pragma unroll
    for (int dj = 0; dj < 8; dj++) {
        int j = tx * 8 + dj;
        float m = Mj[j];
        __half2 h[4];
#pragma unroll
        for (int p = 0; p < 4; p++)
            h[p] = __floats2half2_rn(__expf(acc[2 * p][dj] - m),
                                     __expf(acc[2 * p + 1][dj] - m));
        *(uint4*)(d_E + ((size_t)s * RR + j) * RR + ty * 8) = *(uint4*)h;
    }
}

// ---------------- K5: gold-path scores (unary + pair) --------------------------
__global__ void k_gold(const float* __restrict__ U, const float* __restrict__ Hm,
                       const int* __restrict__ gold, const void* __restrict__ aw) {
    __shared__ float r[4];
    int l = blockIdx.x;
    int tid = threadIdx.x;
    if (tid == 0) atomicAdd(&d_acc[0], (double)U[(size_t)l * NN + gold[l]]);
    if (l < LL - 1) {
        int gp = gold[l], gc = gold[l + 1];
        float s = 0.f;
        for (int k = tid; k < DD; k += 128)
            s += d_HW[(size_t)gp * DD + k] * Hm[(size_t)gc * DD + k];
        for (int o = 16; o > 0; o >>= 1) s += __shfl_xor_sync(~0u, s, o);
        if ((tid & 31) == 0) r[tid >> 5] = s;
        __syncthreads();
        if (tid == 0) {
            float tr = r[0] + r[1] + r[2] + r[3];
            float val = mask_at(aw, (size_t)gc * NN + gp, d_atype) ? tr : PEN;
            atomicAdd(&d_acc[1], (double)val);
        }
    }
}

// ---------------- K4: sequential scan (single persistent block) ----------------
// fp16 E, fp32 a and fp32 accumulation (fp16 accumulation caused an underflow
// cascade: all s_j -> 0 at some step -> alpha all -inf -> logZ -inf -> NaN).
__device__ __forceinline__ void acc4f(float& accf, uint4 u, const float2* a) {
    const __half2* e = (const __half2*)&u;
#pragma unroll
    for (int p = 0; p < 4; p++) {
        float2 ef = __half22float2(e[p]);
        float2 av = a[p];
        accf = fmaf(ef.x, av.x, accf);
        accf = fmaf(ef.y, av.y, accf);
    }
}

__global__ __launch_bounds__(256, 1)
void k_scan(float* __restrict__ out) {
    __shared__ float alpha[2][RR];
    __shared__ __align__(16) float af[RR];
    __shared__ float red[8];
    __shared__ float m_sh;

    int tid = threadIdx.x;
    if (tid < RR) alpha[0][tid] = d_lsm[tid];      // alpha0 = log_softmax(u0[cand0])
    __syncthreads();

    int j = tid >> 1, h = tid & 1;

    for (int s = 0; s < STEPS; s++) {
        // prefetch this step's E slab early (independent of alpha)
        const uint4* ep = (const uint4*)(d_E + ((size_t)s * RR + j) * RR + h * 64);
        uint4 e0 = ep[0], e1 = ep[1], e2 = ep[2], e3 = ep[3];
        uint4 e4 = ep[4], e5 = ep[5], e6 = ep[6], e7 = ep[7];
        float Ms = 0.f, Ls = 0.f;
        if (h == 0) {
            Ms = d_M[s * RR + j];
            Ls = d_lsm[(s + 1) * RR + j];
        }
        int cur = s & 1;

        // max over alpha
        float v = (tid < RR) ? alpha[cur][tid] : -INFINITY;
        for (int o = 16; o > 0; o >>= 1) v = fmaxf(v, __shfl_xor_sync(~0u, v, o));
        if ((tid & 31) == 0) red[tid >> 5] = v;
        __syncthreads();
        if (tid == 0) {
            float m = red[0];
            for (int q = 1; q < 8; q++) m = fmaxf(m, red[q]);
            if (m == -INFINITY) m = 0.f;
            m_sh = m;
        }
        __syncthreads();
        float m = m_sh;
        if (tid < RR) af[tid] = __expf(alpha[cur][tid] - m);   // fp32 a
        __syncthreads();

        // s_j = sum_i a_i * E[j][i] : each (j,h) pair handles 64 i's, fp32 acc
        const float2* ap = (const float2*)(af + h * 64);
        float accf = 0.f;
        acc4f(accf, e0, ap + 0);  acc4f(accf, e1, ap + 4);
        acc4f(accf, e2, ap + 8);  acc4f(accf, e3, ap + 12);
        acc4f(accf, e4, ap + 16); acc4f(accf, e5, ap + 20);
        acc4f(accf, e6, ap + 24); acc4f(accf, e7, ap + 28);
        float sj = accf + __shfl_xor_sync(~0u, accf, 1);

        float nv = 0.f;
        if (h == 0) nv = __logf(fmaxf(sj, 1e-30f)) + m + Ms + Ls;  // floored: never -inf
        __syncthreads();
        if (h == 0) alpha[cur ^ 1][j] = nv;
        __syncthreads();
    }

    // logZ = lse(alpha_last)
    int fin = STEPS & 1;  // 1
    float v = (tid < RR) ? alpha[fin][tid] : -INFINITY;
    for (int o = 16; o > 0; o >>= 1) v = fmaxf(v, __shfl_xor_sync(~0u, v, o));
    if ((tid & 31) == 0) red[tid >> 5] = v;
    __syncthreads();
    if (tid == 0) {
        float m = red[0];
        for (int q = 1; q < 8; q++) m = fmaxf(m, red[q]);
        m_sh = m;
    }
    __syncthreads();
    float m = m_sh;
    float e = (tid < RR) ? __expf(alpha[fin][tid] - m) : 0.f;
    for (int o = 16; o > 0; o >>= 1) e += __shfl_xor_sync(~0u, e, o);
    if ((tid & 31) == 0) red[tid >> 5] = e;
    __syncthreads();
    if (tid == 0) {
        float S = 0.f;
        for (int q = 0; q < 8; q++) S += red[q];
        double logZ = (double)m + log((double)S);
        out[0] = (float)(logZ - (d_acc[0] + d_acc[1]));
    }
}

// ---------------- launch -------------------------------------------------------
extern "C" void kernel_launch(void* const* d_in, const int* in_sizes, int n_in,
                              void* d_out, int out_size) {
    const float* U    = (const float*)d_in[0];   // unary_logits [L, N]
    const float* Hm   = (const float*)d_in[1];   // H [N, D]
    const float* W    = (const float*)d_in[2];   // W [D, D]
    const int*   gold = (const int*)d_in[3];     // gold [L]
    const void*  aw   = d_in[4];                 // allowed [N, N] (dtype detected)

    k_init<<<1, 256>>>((const unsigned*)aw);
    k_topk<<<LL, 256>>>(U);
    k_gemm_hw<<<dim3(4, 128), 256>>>(Hm, W);
    k_pair<<<STEPS, 256>>>(Hm, aw);
    k_gold<<<LL, 128>>>(U, Hm, gold, aw);
    k_scan<<<1, 256>>>((float*)d_out);
}

// round 5
// speedup vs baseline: 1.3439x; 1.3439x over previous
#include <cuda_runtime.h>
#include <cuda_bf16.h>
#include <math.h>

#define LL    1024
#define NN    16384
#define DD    512
#define RR    128
#define PEN   (-10000.0f)
#define STEPS 1023
#define CAP   1536

// tile smem layout (dynamic): As[128][136]bf16 | Bs[128][136]bf16 | prevs[128] | curs[128] | colpart[4][128] | Mj[128]
#define TS        136                 // padded row (elements); 272B row, 16B-aligned, ldmatrix conflict-free
#define AB_BYTES  (128 * TS * 2)      // 34816
#define SMEM_BYTES (2 * AB_BYTES + 128*4 + 128*4 + 4*128*4 + 128*4)   // 73216

// ---------------- scratch ------------------------------------------------------
__device__ __nv_bfloat16 d_Hb[(size_t)NN * DD];      // 16 MB
__device__ __nv_bfloat16 d_HWb[(size_t)NN * DD];     // 16 MB
__device__ __nv_bfloat16 d_Wt[DD * DD];              // W^T, bf16
__device__ __nv_bfloat16 d_E[(size_t)STEPS * RR * RR]; // 33.5 MB : exp(pair-colmax) [s][j][i]
__device__ float   d_M[STEPS * RR];
__device__ int     d_cand[LL * RR];
__device__ float   d_lsm[LL * RR];
__device__ double  d_acc[2];
__device__ int     d_atype;

// ---------------- helpers ------------------------------------------------------
__device__ __forceinline__ unsigned fkey(float f) {
    unsigned u = __float_as_uint(f);
    return (u & 0x80000000u) ? ~u : (u | 0x80000000u);
}
__device__ __forceinline__ bool mask_at(const void* aw, size_t idx, int t) {
    if (t == 0) return ((const unsigned char*)aw)[idx] != 0;
    if (t == 1) return ((const int*)aw)[idx] != 0;
    return ((const float*)aw)[idx] != 0.0f;
}
__device__ __forceinline__ void ldm4(unsigned addr, unsigned* r) {
    asm volatile("ldmatrix.sync.aligned.m8n8.x4.shared.b16 {%0,%1,%2,%3}, [%4];"
                 : "=r"(r[0]), "=r"(r[1]), "=r"(r[2]), "=r"(r[3]) : "r"(addr));
}
__device__ __forceinline__ void mma_bf16(float* d, const unsigned* a, const unsigned* b) {
    asm volatile(
        "mma.sync.aligned.m16n8k16.row.col.f32.bf16.bf16.f32 "
        "{%0,%1,%2,%3},{%4,%5,%6,%7},{%8,%9},{%0,%1,%2,%3};"
        : "+f"(d[0]), "+f"(d[1]), "+f"(d[2]), "+f"(d[3])
        : "r"(a[0]), "r"(a[1]), "r"(a[2]), "r"(a[3]), "r"(b[0]), "r"(b[1]));
}

// ---------------- K0: init + allowed-dtype detection ---------------------------
__global__ void k_init(const unsigned* __restrict__ aw) {
    __shared__ int isF, isB;
    if (threadIdx.x == 0) { isF = 0; isB = 0; d_acc[0] = 0.0; d_acc[1] = 0.0; }
    __syncthreads();
    for (int i = threadIdx.x; i < 4096; i += blockDim.x) {
        unsigned w = aw[i];
        if (w == 0x3F800000u) isF = 1;
        else if (w != 0u && w != 1u) isB = 1;
    }
    __syncthreads();
    if (threadIdx.x == 0) d_atype = isF ? 2 : (isB ? 0 : 1);
}

// ---------------- conversions --------------------------------------------------
__global__ void k_convH(const float* __restrict__ Hm) {
    int i = blockIdx.x * 256 + threadIdx.x;          // over bf16x2 pairs
    float2 v = ((const float2*)Hm)[i];
    ((__nv_bfloat162*)d_Hb)[i] = __floats2bfloat162_rn(v.x, v.y);
}
__global__ void k_convW(const float* __restrict__ W) {
    int i = blockIdx.x * 256 + threadIdx.x;          // i = n*512 + k
    int n = i >> 9, k = i & 511;
    d_Wt[i] = __float2bfloat16(W[k * DD + n]);
}

// ---------------- K1: top-128 (hist pass + collect + rank select) --------------
__global__ void k_topk(const float* __restrict__ U) {
    const int tid = threadIdx.x;
    const int row = blockIdx.x;
    const float* x = U + (size_t)row * NN;

    __shared__ unsigned bins[256];
    __shared__ unsigned keybuf[CAP];
    __shared__ int      idxbuf[CAP];
    __shared__ int s_cnt, s_done;
    __shared__ unsigned s_thresh, s_pref, s_rem;
    __shared__ int   cand_sh[RR];
    __shared__ float val_sh[RR];
    __shared__ float red[16];

    if (tid == 0) { s_done = 0; s_cnt = 0; s_pref = 0u; s_rem = RR; }
    if (tid < RR) { cand_sh[tid] = 0; val_sh[tid] = -INFINITY; }
    __syncthreads();

    for (int pass = 0; pass < 4; ++pass) {
        int shift = 24 - 8 * pass;
        bins[tid] = 0;
        __syncthreads();
        unsigned pmask = pass ? (0xFFFFFFFFu << (shift + 8)) : 0u;
        unsigned pref = s_pref;
        for (int i = tid; i < NN; i += 256) {
            unsigned k = fkey(x[i]);
            if ((k & pmask) == pref) atomicAdd(&bins[(k >> shift) & 0xFFu], 1u);
        }
        __syncthreads();
        if (tid == 0) {
            int r = (int)s_rem;
            int b = 255;
            for (;;) { int c = (int)bins[b]; if (c >= r) break; r -= c; --b; }
            int cge = RR - r + (int)bins[b];      // # elems with key >= bin lower bound
            if (cge <= CAP || pass == 3) { s_thresh = pref | ((unsigned)b << shift); s_done = 1; }
            else { s_pref = pref | ((unsigned)b << shift); s_rem = (unsigned)r; }
        }
        __syncthreads();
        if (s_done) break;
    }

    unsigned th = s_thresh;
    for (int i = tid; i < NN; i += 256) {
        unsigned k = fkey(x[i]);
        if (k >= th) {
            int p = atomicAdd(&s_cnt, 1);
            if (p < CAP) { keybuf[p] = k; idxbuf[p] = i; }
        }
    }
    __syncthreads();
    int cnt = min(s_cnt, CAP);

    // exact rank select with first-index tie-break (matches jax top_k set)
    for (int e = tid; e < cnt; e += 256) {
        unsigned ke = keybuf[e]; int ie = idxbuf[e]; int rank = 0;
        for (int f = 0; f < cnt; f++) {
            unsigned kf = keybuf[f];
            rank += (kf > ke) || (kf == ke && idxbuf[f] < ie);
        }
        if (rank < RR) {
            cand_sh[rank] = ie;
            val_sh[rank] = __uint_as_float((ke & 0x80000000u) ? (ke ^ 0x80000000u) : ~ke);
        }
    }
    __syncthreads();

    // log_softmax over the 128 selected values
    float v = (tid < RR) ? val_sh[tid] : -INFINITY;
    for (int o = 16; o > 0; o >>= 1) v = fmaxf(v, __shfl_xor_sync(~0u, v, o));
    if ((tid & 31) == 0) red[tid >> 5] = v;
    __syncthreads();
    if (tid == 0) {
        float m = red[0];
        for (int q = 1; q < 8; q++) m = fmaxf(m, red[q]);
        if (m == -INFINITY) m = 0.f;
        red[0] = m;
    }
    __syncthreads();
    float mx = red[0];
    float e = (tid < RR) ? __expf(val_sh[tid] - mx) : 0.f;
    for (int o = 16; o > 0; o >>= 1) e += __shfl_xor_sync(~0u, e, o);
    if ((tid & 31) == 0) red[8 + (tid >> 5)] = e;
    __syncthreads();
    if (tid == 0) {
        float s = 0.f;
        for (int q = 0; q < 8; q++) s += red[8 + q];
        red[1] = mx + logf(fmaxf(s, 1e-30f));
    }
    __syncthreads();
    float lse = red[1];
    if (tid < RR) {
        d_cand[row * RR + tid] = cand_sh[tid];
        d_lsm[row * RR + tid] = val_sh[tid] - lse;
    }
}

// ---------------- shared mma core: C[128][128] = Arows @ Brows^T, K=512 --------
// Arows/Brows: pointers to bf16 [*, 512]; rowA/rowB: global row index per tile row.
// acc: float[2][8][4] per thread. 8 warps: wm=wid&3 (32 rows), wn=wid>>2 (64 cols).
struct MmaCtx {
    __nv_bfloat16* As; __nv_bfloat16* Bs;
    unsigned sA, sB;
    int tid, lane, wm, wn;
};

__device__ __forceinline__ void mma_chunks(MmaCtx& cx,
    const __nv_bfloat16* __restrict__ Abase, const int* arows,
    const __nv_bfloat16* __restrict__ Bbase, const int* brows,
    float acc[2][8][4])
{
    int r = cx.tid >> 1, hf = cx.tid & 1;
    for (int c = 0; c < 4; c++) {
        int k0 = c * 128;
        const uint4* srcA = (const uint4*)(Abase + (size_t)arows[r] * DD + k0 + hf * 64);
        const uint4* srcB = (const uint4*)(Bbase + (size_t)brows[r] * DD + k0 + hf * 64);
        uint4* dstA = (uint4*)((char*)cx.As + r * (TS * 2) + hf * 128);
        uint4* dstB = (uint4*)((char*)cx.Bs + r * (TS * 2) + hf * 128);
#pragma unroll
        for (int q = 0; q < 8; q++) { dstA[q] = srcA[q]; dstB[q] = srcB[q]; }
        __syncthreads();

        int r15 = cx.lane & 15, kh = cx.lane >> 4;
        int bn = (cx.lane & 7) + ((cx.lane >> 4) << 3);
        int bkh = (cx.lane >> 3) & 1;
#pragma unroll
        for (int kk = 0; kk < 8; kk++) {
            unsigned Af[2][4], Bf[4][4];
#pragma unroll
            for (int tm = 0; tm < 2; tm++)
                ldm4(cx.sA + (cx.wm * 32 + tm * 16 + r15) * (TS * 2) + kk * 32 + kh * 16, Af[tm]);
#pragma unroll
            for (int t16 = 0; t16 < 4; t16++)
                ldm4(cx.sB + (cx.wn * 64 + t16 * 16 + bn) * (TS * 2) + kk * 32 + bkh * 16, Bf[t16]);
#pragma unroll
            for (int tm = 0; tm < 2; tm++)
#pragma unroll
                for (int tn = 0; tn < 8; tn++)
                    mma_bf16(acc[tm][tn], Af[tm], &Bf[tn >> 1][(tn & 1) * 2]);
        }
        __syncthreads();
    }
}

__device__ __forceinline__ void mma_setup(MmaCtx& cx, char* smem) {
    cx.tid = threadIdx.x; cx.lane = cx.tid & 31;
    int wid = cx.tid >> 5; cx.wm = wid & 3; cx.wn = wid >> 2;
    cx.As = (__nv_bfloat16*)smem;
    cx.Bs = (__nv_bfloat16*)(smem + AB_BYTES);
    cx.sA = (unsigned)__cvta_generic_to_shared(cx.As);
    cx.sB = (unsigned)__cvta_generic_to_shared(cx.Bs);
}

// ---------------- K2: HWb = Hb @ W (tensor cores, bf16 out) --------------------
__global__ __launch_bounds__(256, 2)
void k_hw() {
    extern __shared__ char smem[];
    MmaCtx cx; mma_setup(cx, smem);
    int nt = blockIdx.x, mt = blockIdx.y;

    __shared__ int arows[128], brows[128];
    if (cx.tid < 128) { arows[cx.tid] = mt * 128 + cx.tid; brows[cx.tid] = nt * 128 + cx.tid; }
    __syncthreads();

    float acc[2][8][4];
#pragma unroll
    for (int a = 0; a < 2; a++)
#pragma unroll
        for (int b = 0; b < 8; b++)
#pragma unroll
            for (int q = 0; q < 4; q++) acc[a][b][q] = 0.f;

    mma_chunks(cx, d_Hb, arows, d_Wt, brows, acc);

    // stage C bf16 [row][col] (alias As/Bs region), then coalesced copy-out
    __nv_bfloat16* Cst = (__nv_bfloat16*)smem;
    int g = cx.lane >> 2, tg = cx.lane & 3;
#pragma unroll
    for (int tm = 0; tm < 2; tm++)
#pragma unroll
        for (int tn = 0; tn < 8; tn++)
#pragma unroll
            for (int q = 0; q < 4; q++) {
                int rrow = cx.wm * 32 + tm * 16 + g + (q >> 1) * 8;
                int col = cx.wn * 64 + tn * 8 + tg * 2 + (q & 1);
                Cst[rrow * 128 + col] = __float2bfloat16(acc[tm][tn][q]);
            }
    __syncthreads();
    int r = cx.tid >> 1, hf = cx.tid & 1;
    const uint4* src = (const uint4*)((char*)Cst + r * 256 + hf * 128);
    uint4* dst = (uint4*)(d_HWb + (size_t)(mt * 128 + r) * DD + nt * 128 + hf * 64);
#pragma unroll
    for (int q = 0; q < 8; q++) dst[q] = src[q];
}

// ---------------- K3: pair GEMM + mask + colmax + exp -> bf16 E ----------------
__global__ __launch_bounds__(256, 2)
void k_pair(const void* __restrict__ aw) {
    extern __shared__ char smem[];
    MmaCtx cx; mma_setup(cx, smem);
    int s = blockIdx.x;

    int* prevs = (int*)(smem + 2 * AB_BYTES);
    int* curs = prevs + 128;
    float* colpart = (float*)(curs + 128);   // [4][128]
    float* Mj = colpart + 4 * 128;

    if (cx.tid < 128) {
        prevs[cx.tid] = d_cand[s * RR + cx.tid];
        curs[cx.tid] = d_cand[(s + 1) * RR + cx.tid];
    }
    __syncthreads();

    float acc[2][8][4];
#pragma unroll
    for (int a = 0; a < 2; a++)
#pragma unroll
        for (int b = 0; b < 8; b++)
#pragma unroll
            for (int q = 0; q < 4; q++) acc[a][b][q] = 0.f;

    mma_chunks(cx, d_HWb, prevs, d_Hb, curs, acc);

    // mask + penalty
    int atype = d_atype;
    int g = cx.lane >> 2, tg = cx.lane & 3;
#pragma unroll
    for (int tn = 0; tn < 8; tn++) {
#pragma unroll
        for (int co = 0; co < 2; co++) {
            int col = cx.wn * 64 + tn * 8 + tg * 2 + co;
            size_t base = (size_t)curs[col] * NN;
#pragma unroll
            for (int tm = 0; tm < 2; tm++)
#pragma unroll
                for (int rh = 0; rh < 2; rh++) {
                    int rrow = cx.wm * 32 + tm * 16 + g + rh * 8;
                    if (!mask_at(aw, base + prevs[rrow], atype)) acc[tm][tn][rh * 2 + co] += PEN;
                }
        }
    }

    // per-column max: 4 vals/thread -> shfl over groupID -> colpart[wm][col]
#pragma unroll
    for (int tn = 0; tn < 8; tn++)
#pragma unroll
        for (int co = 0; co < 2; co++) {
            float cm = fmaxf(fmaxf(acc[0][tn][co], acc[0][tn][2 + co]),
                             fmaxf(acc[1][tn][co], acc[1][tn][2 + co]));
            cm = fmaxf(cm, __shfl_xor_sync(~0u, cm, 4));
            cm = fmaxf(cm, __shfl_xor_sync(~0u, cm, 8));
            cm = fmaxf(cm, __shfl_xor_sync(~0u, cm, 16));
            if (g == 0) colpart[cx.wm * 128 + cx.wn * 64 + tn * 8 + tg * 2 + co] = cm;
        }
    __syncthreads();
    if (cx.tid < 128) {
        float m = fmaxf(fmaxf(colpart[cx.tid], colpart[128 + cx.tid]),
                        fmaxf(colpart[256 + cx.tid], colpart[384 + cx.tid]));
        Mj[cx.tid] = m;
        d_M[s * 128 + cx.tid] = m;
    }
    __syncthreads();

    // exp -> bf16, stage [col][row] (alias As/Bs), then coalesced copy-out
    __nv_bfloat16* Est = (__nv_bfloat16*)smem;
#pragma unroll
    for (int tn = 0; tn < 8; tn++)
#pragma unroll
        for (int q = 0; q < 4; q++) {
            int rrow = cx.wm * 32 + ((q >> 1) ? 8 : 0) + g;     // tm folded below
#pragma unroll
            for (int tm = 0; tm < 2; tm++) {
                int rr = cx.wm * 32 + tm * 16 + g + (q >> 1) * 8;
                int col = cx.wn * 64 + tn * 8 + tg * 2 + (q & 1);
                Est[col * 128 + rr] = __float2bfloat16(__expf(acc[tm][tn][q] - Mj[col]));
            }
            (void)rrow;
        }
    __syncthreads();
    const uint4* src = (const uint4*)smem;
    uint4* dst = (uint4*)(d_E + (size_t)s * RR * RR);
    for (int i = cx.tid; i < 2048; i += 256) dst[i] = src[i];
}

// ---------------- K5: gold-path scores -----------------------------------------
__global__ void k_gold(const float* __restrict__ U, const float* __restrict__ Hm,
                       const int* __restrict__ gold, const void* __restrict__ aw) {
    __shared__ float r[4];
    int l = blockIdx.x;
    int tid = threadIdx.x;
    if (tid == 0) atomicAdd(&d_acc[0], (double)U[(size_t)l * NN + gold[l]]);
    if (l < LL - 1) {
        int gp = gold[l], gc = gold[l + 1];
        float s = 0.f;
        for (int k = tid; k < DD; k += 128)
            s += __bfloat162float(d_HWb[(size_t)gp * DD + k]) * Hm[(size_t)gc * DD + k];
        for (int o = 16; o > 0; o >>= 1) s += __shfl_xor_sync(~0u, s, o);
        if ((tid & 31) == 0) r[tid >> 5] = s;
        __syncthreads();
        if (tid == 0) {
            float tr = r[0] + r[1] + r[2] + r[3];
            float val = mask_at(aw, (size_t)gc * NN + gp, d_atype) ? tr : PEN;
            atomicAdd(&d_acc[1], (double)val);
        }
    }
}

// ---------------- K4: sequential scan (single block, bf16 dot, 2 BAR/step) -----
__global__ __launch_bounds__(256, 1)
void k_scan(float* __restrict__ out) {
    __shared__ __align__(16) float alpha[RR];
    __shared__ __align__(16) __nv_bfloat16 ab[RR];
    __shared__ float red[8];
    __shared__ float m_sh;

    int tid = threadIdx.x;
    int lane = tid & 31;
    int j = tid >> 1, h = tid & 1;
    if (tid < RR) alpha[tid] = d_lsm[tid];
    __syncthreads();

    uint4 Ec[8];
    {
        const uint4* p = (const uint4*)(d_E + ((size_t)j * RR + (h << 6)));
#pragma unroll
        for (int q = 0; q < 8; q++) Ec[q] = p[q];
    }
    float Ms = d_M[j], Ls = d_lsm[RR + j];

#pragma unroll 2
    for (int s = 0; s < STEPS; s++) {
        uint4 En[8]; float Msn = 0.f, Lsn = 0.f;
        if (s + 1 < STEPS) {
            const uint4* p = (const uint4*)(d_E + (((size_t)(s + 1) * RR + j) * RR + (h << 6)));
#pragma unroll
            for (int q = 0; q < 8; q++) En[q] = p[q];
            Msn = d_M[(s + 1) * RR + j];
            Lsn = d_lsm[(size_t)(s + 2) * RR + j];
        }

        // warp-redundant max over alpha (no barrier)
        float v = fmaxf(fmaxf(alpha[lane], alpha[lane + 32]),
                        fmaxf(alpha[lane + 64], alpha[lane + 96]));
#pragma unroll
        for (int o = 16; o > 0; o >>= 1) v = fmaxf(v, __shfl_xor_sync(~0u, v, o));
        float m = (v == -INFINITY) ? 0.f : v;

        if (tid < RR) ab[tid] = __float2bfloat16(__expf(alpha[tid] - m));
        __syncthreads();

        // s_j = sum_i a_i E[j][i] over this thread's 64 i's (bf16x2 fma; fp32 range)
        const __nv_bfloat162* ap = (const __nv_bfloat162*)(ab + (h << 6));
        __nv_bfloat162 a2 = __float2bfloat162_rn(0.f);
#pragma unroll
        for (int q = 0; q < 8; q++) {
            const __nv_bfloat162* ev = (const __nv_bfloat162*)&Ec[q];
#pragma unroll
            for (int p = 0; p < 4; p++) a2 = __hfma2(ev[p], ap[q * 4 + p], a2);
        }
        float2 f2 = __bfloat1622float2(a2);
        float sj = f2.x + f2.y;
        sj += __shfl_xor_sync(~0u, sj, 1);

        if (h == 0) alpha[j] = __logf(fmaxf(sj, 1e-30f)) + m + Ms + Ls;

#pragma unroll
        for (int q = 0; q < 8; q++) Ec[q] = En[q];
        Ms = Msn; Ls = Lsn;
        __syncthreads();
    }

    // logZ = lse(alpha)
    float v = (tid < RR) ? alpha[tid] : -INFINITY;
    for (int o = 16; o > 0; o >>= 1) v = fmaxf(v, __shfl_xor_sync(~0u, v, o));
    if ((tid & 31) == 0) red[tid >> 5] = v;
    __syncthreads();
    if (tid == 0) {
        float m = red[0];
        for (int q = 1; q < 8; q++) m = fmaxf(m, red[q]);
        m_sh = m;
    }
    __syncthreads();
    float m = m_sh;
    float e = (tid < RR) ? __expf(alpha[tid] - m) : 0.f;
    for (int o = 16; o > 0; o >>= 1) e += __shfl_xor_sync(~0u, e, o);
    if ((tid & 31) == 0) red[tid >> 5] = e;
    __syncthreads();
    if (tid == 0) {
        float S = 0.f;
        for (int q = 0; q < 8; q++) S += red[q];
        double logZ = (double)m + log((double)S);
        out[0] = (float)(logZ - (d_acc[0] + d_acc[1]));
    }
}

// ---------------- launch -------------------------------------------------------
extern "C" void kernel_launch(void* const* d_in, const int* in_sizes, int n_in,
                              void* d_out, int out_size) {
    const float* U    = (const float*)d_in[0];
    const float* Hm   = (const float*)d_in[1];
    const float* W    = (const float*)d_in[2];
    const int*   gold = (const int*)d_in[3];
    const void*  aw   = d_in[4];

    cudaFuncSetAttribute(k_hw,   cudaFuncAttributeMaxDynamicSharedMemorySize, SMEM_BYTES);
    cudaFuncSetAttribute(k_pair, cudaFuncAttributeMaxDynamicSharedMemorySize, SMEM_BYTES);

    k_init<<<1, 256>>>((const unsigned*)aw);
    k_convH<<<(NN * DD / 2) / 256, 256>>>(Hm);
    k_convW<<<(DD * DD) / 256, 256>>>(W);
    k_topk<<<LL, 256>>>(U);
    k_hw<<<dim3(4, 128), 256, SMEM_BYTES>>>();
    k_pair<<<STEPS, 256, SMEM_BYTES>>>(aw);
    k_gold<<<LL, 128>>>(U, Hm, gold, aw);
    k_scan<<<1, 256>>>((float*)d_out);
}